// round 13
// baseline (speedup 1.0000x reference)
#include <cuda_runtime.h>
#include <cuda_fp16.h>
#include <cstdint>

// ---------------------------------------------------------------------------
// Problem constants
#define NB       4
#define TOK      131072          // T*n tokens per batch
#define C        64
#define NROWS    16384           // n
#define SPLITS   128             // split-K blocks per batch
#define TPS      (TOK / SPLITS)  // 1024 tokens per block
#define STAGE_T  32              // tokens per stage
#define NSTAGES  (TPS / STAGE_T) // 32
#define RPH      72              // plane row stride in u32 (8*lr+lq -> all banks)
#define PLANEU   (16 * RPH)      // u32 per plane (16 token-pairs x 72)
#define BUFU     (4 * PLANEU)    // u32 per buffer (KH0,KH1,VH0,VH1)
#define KV_SMEM_BYTES  (2 * BUFU * 4)              // 36,864 B

#define OROWS    64              // rows per out block
#define SB64     (16 * 68)       // u64 per out B plane in smem
#define SA32     (OROWS * 36)    // u32 per out A plane in smem (row stride 36)
#define OUT_SMEM_BYTES (2 * SB64 * 8 + 2 * SA32 * 4)  // 17,408 + 18,432 = 35,840

// Scratch (no allocations allowed)
__device__ float g_partial[(size_t)NB * SPLITS * C * C];    // 8 MB [b][s][c][d]
__device__ float g_kv[NB * C * C];                          // [b][c][d]
// softmax output pre-split to fp16 (h0,h1) B-planes, alpha folded:
// [b][plane][row=c-quad 16][d 64] u64 = 4 halves {c,c+1 | c+8,c+9}
__device__ unsigned long long g_smh[NB * 2 * 16 * 64];

// ---- helpers ----
__device__ __forceinline__ void stcg2(float* p, float x, float y) {
    asm volatile("st.global.cg.v2.f32 [%0], {%1,%2};" :: "l"(p), "f"(x), "f"(y));
}
__device__ __forceinline__ uint32_t h2u(__half2 h) { return *(uint32_t*)&h; }

// fp16 Dekker split: x = h0 + h1 (+ O(2^-24)); pack token-pair (low = even tok)
__device__ __forceinline__ void split_pair(float a, float b,
                                           uint32_t& h0, uint32_t& h1) {
    __half ha = __float2half_rn(a);
    __half hb = __float2half_rn(b);
    float ra = a - __half2float(ha);
    float rb = b - __half2float(hb);
    __half2 p0 = __halves2half2(ha, hb);
    __half2 p1 = __floats2half2_rn(ra, rb);
    h0 = *(uint32_t*)&p0;
    h1 = *(uint32_t*)&p1;
}

// m16n8k16 fp16 HMMA: D(f32) += A(f16) x B(f16)
__device__ __forceinline__ void mma16(float* d, const uint32_t* a, const uint32_t* b) {
    asm volatile(
        "mma.sync.aligned.m16n8k16.row.col.f32.f16.f16.f32 "
        "{%0,%1,%2,%3}, {%4,%5,%6,%7}, {%8,%9}, {%0,%1,%2,%3};"
        : "+f"(d[0]), "+f"(d[1]), "+f"(d[2]), "+f"(d[3])
        : "r"(a[0]), "r"(a[1]), "r"(a[2]), "r"(a[3]), "r"(b[0]), "r"(b[1]));
}

// ---------------------------------------------------------------------------
// Kernel A: partial kv_mul on fp16 HMMA (m16n8k16, 3-product Dekker split).
// R10-proven structure; ONLY change: occupancy 2 -> 3 (85-reg cap, ~80 demand)
// to cut the 1.73-wave tail to 1.15 waves and absorb barrier bubbles.
// ---------------------------------------------------------------------------
__global__ __launch_bounds__(256, 3) void kv_partial_kernel(
    const float* __restrict__ Kg, const float* __restrict__ Vg)
{
    extern __shared__ __align__(16) uint32_t su[];

    const int b   = blockIdx.y;
    const int sp  = blockIdx.x;
    const int tid = threadIdx.x;
    const int w   = tid >> 5;
    const int l   = tid & 31;
    const int lr  = l & 3;          // tid-in-group (k dimension)
    const int lq  = l >> 2;         // group id     (m / n dimension)
    const int c0  = (w & 3) * 16;   // warp c origin
    const int d0  = (w >> 2) * 32;  // warp d origin

    // staging: thread handles token-pair tp at 16B chunk c4 for K and V
    const int tp  = tid >> 4;       // 0..15
    const int c4  = tid & 15;
    const int goff = (2 * tp) * C + c4 * 4;      // token 2tp ; +C -> 2tp+1
    const int dstu = tp * RPH + c4 * 4;          // u32 offset within plane

    const float* Kbase = Kg + ((size_t)b * TOK + (size_t)sp * TPS) * C;
    const float* Vbase = Vg + ((size_t)b * TOK + (size_t)sp * TPS) * C;

    float4 pf[4];   // K(2tp), K(2tp+1), V(2tp), V(2tp+1)

    // convert+store one stage of this thread's data into buffer `bu`
    auto stash = [&](uint32_t* bu) {
        uint32_t kh0[4], kh1[4], vh0[4], vh1[4];
        const float* ka = (const float*)&pf[0];
        const float* kb = (const float*)&pf[1];
        const float* va = (const float*)&pf[2];
        const float* vb = (const float*)&pf[3];
        #pragma unroll
        for (int j = 0; j < 4; ++j) {
            split_pair(ka[j], kb[j], kh0[j], kh1[j]);
            split_pair(va[j], vb[j], vh0[j], vh1[j]);
        }
        *(uint4*)&bu[dstu]              = *(uint4*)kh0;
        *(uint4*)&bu[PLANEU + dstu]     = *(uint4*)kh1;
        *(uint4*)&bu[2 * PLANEU + dstu] = *(uint4*)vh0;
        *(uint4*)&bu[3 * PLANEU + dstu] = *(uint4*)vh1;
    };

    // prologue: stage 0 -> regs -> buf0 ; stage 1 -> regs
    pf[0] = *(const float4*)(Kbase + goff);
    pf[1] = *(const float4*)(Kbase + goff + C);
    pf[2] = *(const float4*)(Vbase + goff);
    pf[3] = *(const float4*)(Vbase + goff + C);
    stash(su);
    pf[0] = *(const float4*)(Kbase + goff + STAGE_T * C);
    pf[1] = *(const float4*)(Kbase + goff + STAGE_T * C + C);
    pf[2] = *(const float4*)(Vbase + goff + STAGE_T * C);
    pf[3] = *(const float4*)(Vbase + goff + STAGE_T * C + C);
    __syncthreads();

    float acc[4][4];                 // [n-chunk][frag reg]
    #pragma unroll
    for (int i = 0; i < 4; ++i)
        #pragma unroll
        for (int j = 0; j < 4; ++j) acc[i][j] = 0.f;

    #pragma unroll 1
    for (int it = 0; it < NSTAGES; ++it) {
        // stash stage it+1 into the buffer freed by stage it-1
        if (it + 1 < NSTAGES) stash(&su[((it + 1) & 1) * BUFU]);
        // prefetch stage it+2 into regs
        if (it + 2 < NSTAGES) {
            const int adv = (it + 2) * STAGE_T * C;
            pf[0] = *(const float4*)(Kbase + goff + adv);
            pf[1] = *(const float4*)(Kbase + goff + adv + C);
            pf[2] = *(const float4*)(Vbase + goff + adv);
            pf[3] = *(const float4*)(Vbase + goff + adv + C);
        }

        const uint32_t* kh0p = &su[(it & 1) * BUFU];
        const uint32_t* kh1p = kh0p + PLANEU;
        const uint32_t* vh0p = kh0p + 2 * PLANEU;
        const uint32_t* vh1p = kh0p + 3 * PLANEU;

        #pragma unroll
        for (int ch = 0; ch < 2; ++ch) {
            const int ra = (ch * 8 + lr) * RPH;       // k = 2lr, 2lr+1
            const int rb = (ch * 8 + lr + 4) * RPH;   // k = 2lr+8, 2lr+9
            uint32_t ah0[4], ah1[4];
            ah0[0] = kh0p[ra + c0 + lq];
            ah0[1] = kh0p[ra + c0 + lq + 8];
            ah0[2] = kh0p[rb + c0 + lq];
            ah0[3] = kh0p[rb + c0 + lq + 8];
            ah1[0] = kh1p[ra + c0 + lq];
            ah1[1] = kh1p[ra + c0 + lq + 8];
            ah1[2] = kh1p[rb + c0 + lq];
            ah1[3] = kh1p[rb + c0 + lq + 8];
            #pragma unroll
            for (int nn = 0; nn < 4; ++nn) {
                const int col = d0 + nn * 8 + lq;
                uint32_t bh0[2], bh1[2];
                bh0[0] = vh0p[ra + col];
                bh0[1] = vh0p[rb + col];
                bh1[0] = vh1p[ra + col];
                bh1[1] = vh1p[rb + col];
                mma16(acc[nn], ah0, bh0);
                mma16(acc[nn], ah0, bh1);
                mma16(acc[nn], ah1, bh0);
            }
        }
        __syncthreads();   // compute of it done everywhere; STS of it+1 drained
    }

    // epilogue: C fragment -> g_partial[b][sp][c][d]  (disjoint per warp)
    float* outp = &g_partial[((size_t)(b * SPLITS + sp)) * (C * C)];
    const int row0 = c0 + lq;
    const int row1 = row0 + 8;
    #pragma unroll
    for (int nn = 0; nn < 4; ++nn) {
        const int col = d0 + nn * 8 + 2 * lr;
        stcg2(&outp[row0 * C + col], acc[nn][0], acc[nn][1]);
        stcg2(&outp[row1 * C + col], acc[nn][2], acc[nn][3]);
    }
}

// ---------------------------------------------------------------------------
// Kernel B: deterministic split reduction (float4, fixed order).
// ---------------------------------------------------------------------------
__global__ __launch_bounds__(128, 1) void kv_reduce_kernel()
{
    int q = blockIdx.x * 128 + threadIdx.x;   // 0..4095 float4 index
    int b  = q >> 10;
    int e4 = q & 1023;
    const float4* p = (const float4*)&g_partial[(size_t)b * SPLITS * (C * C)] + e4;
    float4 s0 = make_float4(0.f,0.f,0.f,0.f), s1 = s0, s2 = s0, s3 = s0;
    float4 s4 = s0, s5 = s0, s6 = s0, s7 = s0;
    #pragma unroll 2
    for (int i = 0; i < SPLITS; i += 8) {
        float4 t0 = p[(size_t)(i    ) * 1024];
        float4 t1 = p[(size_t)(i + 1) * 1024];
        float4 t2 = p[(size_t)(i + 2) * 1024];
        float4 t3 = p[(size_t)(i + 3) * 1024];
        float4 t4 = p[(size_t)(i + 4) * 1024];
        float4 t5 = p[(size_t)(i + 5) * 1024];
        float4 t6 = p[(size_t)(i + 6) * 1024];
        float4 t7 = p[(size_t)(i + 7) * 1024];
        s0.x += t0.x; s0.y += t0.y; s0.z += t0.z; s0.w += t0.w;
        s1.x += t1.x; s1.y += t1.y; s1.z += t1.z; s1.w += t1.w;
        s2.x += t2.x; s2.y += t2.y; s2.z += t2.z; s2.w += t2.w;
        s3.x += t3.x; s3.y += t3.y; s3.z += t3.z; s3.w += t3.w;
        s4.x += t4.x; s4.y += t4.y; s4.z += t4.z; s4.w += t4.w;
        s5.x += t5.x; s5.y += t5.y; s5.z += t5.z; s5.w += t5.w;
        s6.x += t6.x; s6.y += t6.y; s6.z += t6.z; s6.w += t6.w;
        s7.x += t7.x; s7.y += t7.y; s7.z += t7.z; s7.w += t7.w;
    }
    float4 r;
    r.x = ((s0.x + s1.x) + (s2.x + s3.x)) + ((s4.x + s5.x) + (s6.x + s7.x));
    r.y = ((s0.y + s1.y) + (s2.y + s3.y)) + ((s4.y + s5.y) + (s6.y + s7.y));
    r.z = ((s0.z + s1.z) + (s2.z + s3.z)) + ((s4.z + s5.z) + (s6.z + s7.z));
    r.w = ((s0.w + s1.w) + (s2.w + s3.w)) + ((s4.w + s5.w) + (s6.w + s7.w));
    ((float4*)g_kv)[q] = r;
}

// ---------------------------------------------------------------------------
// Kernel C: softmax over the C axis, alpha folded; emits fp16 (h0,h1) split
// B-planes g_smh[b][plane][c-quad row][d] for the out GEMM.
// ---------------------------------------------------------------------------
__global__ void softmax_kernel(const float* __restrict__ alpha)
{
    int tid = threadIdx.x;
    int b = tid >> 6;
    int d = tid & 63;
    const float* in = &g_kv[b * (C * C) + d];

    float v[C];
    float m = -3.402823466e38f;
    #pragma unroll
    for (int c = 0; c < C; ++c) { v[c] = in[c * C]; m = fmaxf(m, v[c]); }
    float sum = 0.f;
    #pragma unroll
    for (int c = 0; c < C; ++c) { v[c] = expf(v[c] - m); sum += v[c]; }
    float sc = alpha[0] / sum;
    #pragma unroll
    for (int c = 0; c < C; ++c) v[c] *= sc;

    uint2* g0 = (uint2*)&g_smh[((size_t)b * 2 + 0) * 16 * 64];
    uint2* g1 = (uint2*)&g_smh[((size_t)b * 2 + 1) * 16 * 64];
    #pragma unroll
    for (int row = 0; row < 16; ++row) {
        const int cb = 16 * (row >> 2) + 2 * (row & 3);
        __half2 h0a = __floats2half2_rn(v[cb],     v[cb + 1]);
        __half2 h0b = __floats2half2_rn(v[cb + 8], v[cb + 9]);
        float r0 = v[cb]     - __low2float(h0a);
        float r1 = v[cb + 1] - __high2float(h0a);
        float r8 = v[cb + 8] - __low2float(h0b);
        float r9 = v[cb + 9] - __high2float(h0b);
        __half2 h1a = __floats2half2_rn(r0, r1);
        __half2 h1b = __floats2half2_rn(r8, r9);
        g0[row * 64 + d] = make_uint2(h2u(h0a), h2u(h0b));
        g1[row * 64 + d] = make_uint2(h2u(h1a), h2u(h1b));
    }
}

// ---------------------------------------------------------------------------
// Kernel D: out[b,r,d] = sum_c key_cur[b,r,c] * sm[b,c,d] + val_cur, on HMMA.
// R11-proven fragment math; ONLY change: 64 rows/block (grid 1024, finer
// tiles pack the 592 occ-4 slots -> less tail), warp = one 16-row m-tile.
// ---------------------------------------------------------------------------
__global__ __launch_bounds__(128, 4) void out_kernel(
    const float* __restrict__ key_cur, const float* __restrict__ val_cur,
    float* __restrict__ out)
{
    extern __shared__ __align__(16) uint2 so[];
    uint2*    SB0 = so;                       // [16][68] u64
    uint2*    SB1 = so + SB64;
    uint32_t* SA0 = (uint32_t*)(so + 2 * SB64);   // [64][36] u32
    uint32_t* SA1 = SA0 + SA32;

    const int b   = blockIdx.y;
    const int rb  = blockIdx.x;       // 0..255 (64 rows each)
    const int tid = threadIdx.x;
    const int w   = tid >> 5;
    const int l   = tid & 31;
    const int lr  = l & 3;
    const int lq  = l >> 2;
    const size_t row_base = (size_t)b * NROWS + (size_t)rb * OROWS;

    // load B planes (2 x 1024 u64) from g_smh
    const uint2* gb = (const uint2*)&g_smh[(size_t)b * 2 * 16 * 64];
    #pragma unroll
    for (int k = 0; k < 16; ++k) {
        int idx = k * 128 + tid;          // 0..2047
        int pl  = idx >> 10;
        int rc  = idx & 1023;
        int rr  = rc >> 6, cc = rc & 63;
        (pl ? SB1 : SB0)[rr * 68 + cc] = gb[pl * 1024 + rr * 64 + cc];
    }

    // stage A: 64 key_cur rows -> half2 channel-pair planes (8 float4/thread)
    {
        const int rq = tid >> 4, c4 = tid & 15;
        #pragma unroll
        for (int i = 0; i < 8; ++i) {
            const int r = i * 8 + rq;
            float4 f = *(const float4*)&key_cur[(row_base + r) * C + c4 * 4];
            __half2 p0 = __floats2half2_rn(f.x, f.y);
            __half2 p1 = __floats2half2_rn(f.z, f.w);
            float r0 = f.x - __low2float(p0);
            float r1 = f.y - __high2float(p0);
            float r2 = f.z - __low2float(p1);
            float r3 = f.w - __high2float(p1);
            __half2 q0 = __floats2half2_rn(r0, r1);
            __half2 q1 = __floats2half2_rn(r2, r3);
            *(uint2*)&SA0[r * 36 + 2 * c4] = make_uint2(h2u(p0), h2u(p1));
            *(uint2*)&SA1[r * 36 + 2 * c4] = make_uint2(h2u(q0), h2u(q1));
        }
    }
    __syncthreads();

    float acc[8][4];     // [n-tile][frag reg]
    #pragma unroll
    for (int nn = 0; nn < 8; ++nn)
        #pragma unroll
        for (int j = 0; j < 4; ++j) acc[nn][j] = 0.f;

    #pragma unroll
    for (int qc = 0; qc < 4; ++qc) {
        uint32_t ah0[4], ah1[4];
        const int ra = w * 16 + lq;
        const int cp = qc * 8 + lr;
        ah0[0] = SA0[ra * 36 + cp];
        ah0[1] = SA0[(ra + 8) * 36 + cp];
        ah0[2] = SA0[ra * 36 + cp + 4];
        ah0[3] = SA0[(ra + 8) * 36 + cp + 4];
        ah1[0] = SA1[ra * 36 + cp];
        ah1[1] = SA1[(ra + 8) * 36 + cp];
        ah1[2] = SA1[ra * 36 + cp + 4];
        ah1[3] = SA1[(ra + 8) * 36 + cp + 4];
        #pragma unroll
        for (int nn = 0; nn < 8; ++nn) {
            uint2 B0 = SB0[(4 * qc + lr) * 68 + nn * 8 + lq];
            uint2 B1 = SB1[(4 * qc + lr) * 68 + nn * 8 + lq];
            uint32_t b0[2] = {B0.x, B0.y};
            uint32_t b1[2] = {B1.x, B1.y};
            mma16(acc[nn], ah0, b0);
            mma16(acc[nn], ah0, b1);
            mma16(acc[nn], ah1, b0);
        }
    }

    // epilogue: add val_cur, store
    const size_t r0g = row_base + w * 16 + lq;
    const size_t r1g = r0g + 8;
    #pragma unroll
    for (int nn = 0; nn < 8; ++nn) {
        const int col = nn * 8 + 2 * lr;
        float2 v0 = *(const float2*)&val_cur[r0g * C + col];
        float2 v1 = *(const float2*)&val_cur[r1g * C + col];
        stcg2(&out[r0g * C + col], acc[nn][0] + v0.x, acc[nn][1] + v0.y);
        stcg2(&out[r1g * C + col], acc[nn][2] + v1.x, acc[nn][3] + v1.y);
    }
}

// ---------------------------------------------------------------------------
extern "C" void kernel_launch(void* const* d_in, const int* in_sizes, int n_in,
                              void* d_out, int out_size)
{
    const float* key_mem = (const float*)d_in[0];
    const float* val_mem = (const float*)d_in[1];
    const float* key_cur = (const float*)d_in[2];
    const float* val_cur = (const float*)d_in[3];
    const float* alpha   = (const float*)d_in[4];
    float* out = (float*)d_out;

    cudaFuncSetAttribute(kv_partial_kernel,
                         cudaFuncAttributeMaxDynamicSharedMemorySize, KV_SMEM_BYTES);
    cudaFuncSetAttribute(out_kernel,
                         cudaFuncAttributeMaxDynamicSharedMemorySize, OUT_SMEM_BYTES);

    kv_partial_kernel<<<dim3(SPLITS, NB), 256, KV_SMEM_BYTES>>>(key_mem, val_mem);
    kv_reduce_kernel<<<32, 128>>>();
    softmax_kernel<<<1, 256>>>(alpha);
    out_kernel<<<dim3(NROWS / OROWS, NB), 128, OUT_SMEM_BYTES>>>(key_cur, val_cur, out);
}

// round 15
// speedup vs baseline: 1.0277x; 1.0277x over previous
#include <cuda_runtime.h>
#include <cuda_fp16.h>
#include <cstdint>

// ---------------------------------------------------------------------------
// Problem constants
#define NB       4
#define TOK      131072          // T*n tokens per batch
#define C        64
#define NROWS    16384           // n
#define SPLITS   128             // split-K blocks per batch
#define TPS      (TOK / SPLITS)  // 1024 tokens per block
#define STAGE_T  64              // tokens per stage (16 barriers vs 32)
#define NSTAGES  (TPS / STAGE_T) // 16
#define RPH      72              // plane row stride in u32 (8*lr+lq -> all banks)
#define PLANEU   (32 * RPH)      // u32 per plane (32 token-pairs x 72)
#define BUFU     (4 * PLANEU)    // u32 per buffer (KH0,KH1,VH0,VH1)
#define KV_SMEM_BYTES  (2 * BUFU * 4)              // 73,728 B

#define OROWS    64              // rows per out block
#define SB64     (16 * 68)       // u64 per out B plane in smem
#define SA32     (OROWS * 36)    // u32 per out A plane in smem (row stride 36)
#define SVALF    (OROWS * 68)    // floats for val_cur smem stage
#define OUT_SMEM_BYTES (2 * SB64 * 8 + 2 * SA32 * 4 + SVALF * 4)  // 53,248 B

// Scratch (no allocations allowed)
__device__ float g_partial[(size_t)NB * SPLITS * C * C];    // 8 MB [b][s][c][d]
__device__ float g_kv[NB * C * C];                          // [b][c][d]
// softmax output pre-split to fp16 (h0,h1) B-planes, alpha folded:
// [b][plane][row=c-quad 16][d 64] u64 = 4 halves {c,c+1 | c+8,c+9}
__device__ unsigned long long g_smh[NB * 2 * 16 * 64];

// ---- helpers ----
__device__ __forceinline__ void stcg2(float* p, float x, float y) {
    asm volatile("st.global.cg.v2.f32 [%0], {%1,%2};" :: "l"(p), "f"(x), "f"(y));
}
__device__ __forceinline__ uint32_t h2u(__half2 h) { return *(uint32_t*)&h; }
__device__ __forceinline__ void cp16(unsigned dst, const float* src) {
    asm volatile("cp.async.ca.shared.global [%0], [%1], 16;" :: "r"(dst), "l"(src));
}
__device__ __forceinline__ void cp_commit() {
    asm volatile("cp.async.commit_group;");
}
template <int N>
__device__ __forceinline__ void cp_wait() {
    asm volatile("cp.async.wait_group %0;" :: "n"(N));
}

// fp16 Dekker split: x = h0 + h1 (+ O(2^-24)); pack token-pair (low = even tok)
__device__ __forceinline__ void split_pair(float a, float b,
                                           uint32_t& h0, uint32_t& h1) {
    __half ha = __float2half_rn(a);
    __half hb = __float2half_rn(b);
    float ra = a - __half2float(ha);
    float rb = b - __half2float(hb);
    __half2 p0 = __halves2half2(ha, hb);
    __half2 p1 = __floats2half2_rn(ra, rb);
    h0 = *(uint32_t*)&p0;
    h1 = *(uint32_t*)&p1;
}

// m16n8k16 fp16 HMMA: D(f32) += A(f16) x B(f16)
__device__ __forceinline__ void mma16(float* d, const uint32_t* a, const uint32_t* b) {
    asm volatile(
        "mma.sync.aligned.m16n8k16.row.col.f32.f16.f16.f32 "
        "{%0,%1,%2,%3}, {%4,%5,%6,%7}, {%8,%9}, {%0,%1,%2,%3};"
        : "+f"(d[0]), "+f"(d[1]), "+f"(d[2]), "+f"(d[3])
        : "r"(a[0]), "r"(a[1]), "r"(a[2]), "r"(a[3]), "r"(b[0]), "r"(b[1]));
}

// ---------------------------------------------------------------------------
// Kernel A: partial kv_mul on fp16 HMMA (m16n8k16, 3-product Dekker split).
// R10-proven fragment math; 64-token stages (16 barriers vs 32).
// Each thread stages TWO token-pairs (tp and tp+16). Warp does 48 MMA/stage.
// ---------------------------------------------------------------------------
__global__ __launch_bounds__(256, 2) void kv_partial_kernel(
    const float* __restrict__ Kg, const float* __restrict__ Vg)
{
    extern __shared__ __align__(16) uint32_t su[];

    const int b   = blockIdx.y;
    const int sp  = blockIdx.x;
    const int tid = threadIdx.x;
    const int w   = tid >> 5;
    const int l   = tid & 31;
    const int lr  = l & 3;          // tid-in-group (k dimension)
    const int lq  = l >> 2;         // group id     (m / n dimension)
    const int c0  = (w & 3) * 16;   // warp c origin
    const int d0  = (w >> 2) * 32;  // warp d origin

    // staging: thread handles token-pairs tp and tp+16 at 16B chunk c4
    const int tp  = tid >> 4;       // 0..15
    const int c4  = tid & 15;
    const int goffA = (2 * tp) * C + c4 * 4;        // token 2tp ; +C -> 2tp+1
    const int goffB = goffA + 32 * C;               // token 2tp+32
    const int dstuA = tp * RPH + c4 * 4;
    const int dstuB = (tp + 16) * RPH + c4 * 4;

    const float* Kbase = Kg + ((size_t)b * TOK + (size_t)sp * TPS) * C;
    const float* Vbase = Vg + ((size_t)b * TOK + (size_t)sp * TPS) * C;

    float4 pf[8];   // K(2tp),K(2tp+1),V(2tp),V(2tp+1), K(2tp+32),K(2tp+33),V,V

    #define KV_LDG(adv) do {                                          \
        pf[0] = *(const float4*)(Kbase + goffA + (adv));              \
        pf[1] = *(const float4*)(Kbase + goffA + (adv) + C);          \
        pf[2] = *(const float4*)(Vbase + goffA + (adv));              \
        pf[3] = *(const float4*)(Vbase + goffA + (adv) + C);          \
        pf[4] = *(const float4*)(Kbase + goffB + (adv));              \
        pf[5] = *(const float4*)(Kbase + goffB + (adv) + C);          \
        pf[6] = *(const float4*)(Vbase + goffB + (adv));              \
        pf[7] = *(const float4*)(Vbase + goffB + (adv) + C);          \
    } while (0)

    // convert+store one stage of this thread's data into buffer `bu`
    auto stash = [&](uint32_t* bu) {
        #pragma unroll
        for (int gsel = 0; gsel < 2; ++gsel) {
            uint32_t kh0[4], kh1[4], vh0[4], vh1[4];
            const float* ka = (const float*)&pf[gsel * 4 + 0];
            const float* kb = (const float*)&pf[gsel * 4 + 1];
            const float* va = (const float*)&pf[gsel * 4 + 2];
            const float* vb = (const float*)&pf[gsel * 4 + 3];
            #pragma unroll
            for (int j = 0; j < 4; ++j) {
                split_pair(ka[j], kb[j], kh0[j], kh1[j]);
                split_pair(va[j], vb[j], vh0[j], vh1[j]);
            }
            const int dstu = gsel ? dstuB : dstuA;
            *(uint4*)&bu[dstu]              = *(uint4*)kh0;
            *(uint4*)&bu[PLANEU + dstu]     = *(uint4*)kh1;
            *(uint4*)&bu[2 * PLANEU + dstu] = *(uint4*)vh0;
            *(uint4*)&bu[3 * PLANEU + dstu] = *(uint4*)vh1;
        }
    };

    // prologue: stage 0 -> regs -> buf0 ; stage 1 -> regs
    KV_LDG(0);
    stash(su);
    KV_LDG(STAGE_T * C);
    __syncthreads();

    float acc[4][4];                 // [n-chunk][frag reg]
    #pragma unroll
    for (int i = 0; i < 4; ++i)
        #pragma unroll
        for (int j = 0; j < 4; ++j) acc[i][j] = 0.f;

    #pragma unroll 1
    for (int it = 0; it < NSTAGES; ++it) {
        // stash stage it+1 into the buffer freed by stage it-1
        if (it + 1 < NSTAGES) stash(&su[((it + 1) & 1) * BUFU]);
        // prefetch stage it+2 into regs
        if (it + 2 < NSTAGES) KV_LDG((it + 2) * STAGE_T * C);

        const uint32_t* kh0p = &su[(it & 1) * BUFU];
        const uint32_t* kh1p = kh0p + PLANEU;
        const uint32_t* vh0p = kh0p + 2 * PLANEU;
        const uint32_t* vh1p = kh0p + 3 * PLANEU;

        #pragma unroll
        for (int ch = 0; ch < 4; ++ch) {
            const int ra = (ch * 8 + lr) * RPH;       // k = 2lr, 2lr+1
            const int rb = (ch * 8 + lr + 4) * RPH;   // k = 2lr+8, 2lr+9
            uint32_t ah0[4], ah1[4];
            ah0[0] = kh0p[ra + c0 + lq];
            ah0[1] = kh0p[ra + c0 + lq + 8];
            ah0[2] = kh0p[rb + c0 + lq];
            ah0[3] = kh0p[rb + c0 + lq + 8];
            ah1[0] = kh1p[ra + c0 + lq];
            ah1[1] = kh1p[ra + c0 + lq + 8];
            ah1[2] = kh1p[rb + c0 + lq];
            ah1[3] = kh1p[rb + c0 + lq + 8];
            #pragma unroll
            for (int nn = 0; nn < 4; ++nn) {
                const int col = d0 + nn * 8 + lq;
                uint32_t bh0[2], bh1[2];
                bh0[0] = vh0p[ra + col];
                bh0[1] = vh0p[rb + col];
                bh1[0] = vh1p[ra + col];
                bh1[1] = vh1p[rb + col];
                mma16(acc[nn], ah0, bh0);
                mma16(acc[nn], ah0, bh1);
                mma16(acc[nn], ah1, bh0);
            }
        }
        __syncthreads();   // compute of it done everywhere; STS of it+1 drained
    }
    #undef KV_LDG

    // epilogue: C fragment -> g_partial[b][sp][c][d]  (disjoint per warp)
    float* outp = &g_partial[((size_t)(b * SPLITS + sp)) * (C * C)];
    const int row0 = c0 + lq;
    const int row1 = row0 + 8;
    #pragma unroll
    for (int nn = 0; nn < 4; ++nn) {
        const int col = d0 + nn * 8 + 2 * lr;
        stcg2(&outp[row0 * C + col], acc[nn][0], acc[nn][1]);
        stcg2(&outp[row1 * C + col], acc[nn][2], acc[nn][3]);
    }
}

// ---------------------------------------------------------------------------
// Kernel B: deterministic split reduction v2 (FIXED grid math).
// 128 blocks x 128 thr; 32 blocks per batch, block covers 32 consecutive
// float4 (lane = one float4). Warp j sums splits [32j, 32j+32) coalesced,
// then a fixed-order smem combine: r = (w0+w1)+(w2+w3). Fully in-bounds:
// 32 blocks x 32 float4 = 1024 float4 = one batch's kv matrix.
// ---------------------------------------------------------------------------
__global__ __launch_bounds__(128, 8) void kv_reduce_kernel()
{
    __shared__ float4 sums[4][32];

    const int bb   = blockIdx.x;          // 0..127
    const int b    = bb >> 5;             // batch 0..3
    const int e4   = (bb & 31) * 32;      // float4 base within batch (0..992)
    const int w    = threadIdx.x >> 5;
    const int lane = threadIdx.x & 31;

    const float4* p = (const float4*)&g_partial[(size_t)b * SPLITS * (C * C)]
                    + e4 + lane;
    float4 s0 = make_float4(0.f, 0.f, 0.f, 0.f), s1 = s0, s2 = s0, s3 = s0;
    const int base = w * 32;
    #pragma unroll 2
    for (int i = 0; i < 32; i += 4) {
        float4 t0 = p[(size_t)(base + i    ) * 1024];
        float4 t1 = p[(size_t)(base + i + 1) * 1024];
        float4 t2 = p[(size_t)(base + i + 2) * 1024];
        float4 t3 = p[(size_t)(base + i + 3) * 1024];
        s0.x += t0.x; s0.y += t0.y; s0.z += t0.z; s0.w += t0.w;
        s1.x += t1.x; s1.y += t1.y; s1.z += t1.z; s1.w += t1.w;
        s2.x += t2.x; s2.y += t2.y; s2.z += t2.z; s2.w += t2.w;
        s3.x += t3.x; s3.y += t3.y; s3.z += t3.z; s3.w += t3.w;
    }
    float4 ws;
    ws.x = (s0.x + s1.x) + (s2.x + s3.x);
    ws.y = (s0.y + s1.y) + (s2.y + s3.y);
    ws.z = (s0.z + s1.z) + (s2.z + s3.z);
    ws.w = (s0.w + s1.w) + (s2.w + s3.w);
    sums[w][lane] = ws;
    __syncthreads();

    if (w == 0) {
        float4 a = sums[0][lane], b2 = sums[1][lane];
        float4 c = sums[2][lane], d = sums[3][lane];
        float4 r;
        r.x = (a.x + b2.x) + (c.x + d.x);
        r.y = (a.y + b2.y) + (c.y + d.y);
        r.z = (a.z + b2.z) + (c.z + d.z);
        r.w = (a.w + b2.w) + (c.w + d.w);
        ((float4*)g_kv)[(size_t)b * 1024 + e4 + lane] = r;
    }
}

// ---------------------------------------------------------------------------
// Kernel C: softmax over the C axis, alpha folded; emits fp16 (h0,h1) split
// B-planes g_smh[b][plane][c-quad row][d] for the out GEMM.
// ---------------------------------------------------------------------------
__global__ void softmax_kernel(const float* __restrict__ alpha)
{
    int tid = threadIdx.x;
    int b = tid >> 6;
    int d = tid & 63;
    const float* in = &g_kv[b * (C * C) + d];

    float v[C];
    float m = -3.402823466e38f;
    #pragma unroll
    for (int c = 0; c < C; ++c) { v[c] = in[c * C]; m = fmaxf(m, v[c]); }
    float sum = 0.f;
    #pragma unroll
    for (int c = 0; c < C; ++c) { v[c] = expf(v[c] - m); sum += v[c]; }
    float sc = alpha[0] / sum;
    #pragma unroll
    for (int c = 0; c < C; ++c) v[c] *= sc;

    uint2* g0 = (uint2*)&g_smh[((size_t)b * 2 + 0) * 16 * 64];
    uint2* g1 = (uint2*)&g_smh[((size_t)b * 2 + 1) * 16 * 64];
    #pragma unroll
    for (int row = 0; row < 16; ++row) {
        const int cb = 16 * (row >> 2) + 2 * (row & 3);
        __half2 h0a = __floats2half2_rn(v[cb],     v[cb + 1]);
        __half2 h0b = __floats2half2_rn(v[cb + 8], v[cb + 9]);
        float r0 = v[cb]     - __low2float(h0a);
        float r1 = v[cb + 1] - __high2float(h0a);
        float r8 = v[cb + 8] - __low2float(h0b);
        float r9 = v[cb + 9] - __high2float(h0b);
        __half2 h1a = __floats2half2_rn(r0, r1);
        __half2 h1b = __floats2half2_rn(r8, r9);
        g0[row * 64 + d] = make_uint2(h2u(h0a), h2u(h0b));
        g1[row * 64 + d] = make_uint2(h2u(h1a), h2u(h1b));
    }
}

// ---------------------------------------------------------------------------
// Kernel D: out[b,r,d] = sum_c key_cur[b,r,c] * sm[b,c,d] + val_cur, on HMMA.
// R13-proven structure; val_cur prefetched into smem via cp.async at kernel
// entry (overlaps B/A staging), epilogue reads smem.
// ---------------------------------------------------------------------------
__global__ __launch_bounds__(128, 4) void out_kernel(
    const float* __restrict__ key_cur, const float* __restrict__ val_cur,
    float* __restrict__ out)
{
    extern __shared__ __align__(16) uint2 so[];
    uint2*    SB0 = so;                           // [16][68] u64
    uint2*    SB1 = so + SB64;
    uint32_t* SA0 = (uint32_t*)(so + 2 * SB64);   // [64][36] u32
    uint32_t* SA1 = SA0 + SA32;
    float*    SV  = (float*)(SA1 + SA32);         // [64][68] floats

    const int b   = blockIdx.y;
    const int rb  = blockIdx.x;       // 0..255 (64 rows each)
    const int tid = threadIdx.x;
    const int w   = tid >> 5;
    const int l   = tid & 31;
    const int lr  = l & 3;
    const int lq  = l >> 2;
    const size_t row_base = (size_t)b * NROWS + (size_t)rb * OROWS;

    // val_cur prefetch: 1024 16B-chunks / 128 thr = 8 each (async)
    #pragma unroll
    for (int j = 0; j < 8; ++j) {
        int ch  = j * 128 + tid;
        int row = ch >> 4, c4 = ch & 15;
        cp16((unsigned)__cvta_generic_to_shared(&SV[row * 68 + c4 * 4]),
             &val_cur[(row_base + row) * C + c4 * 4]);
    }
    cp_commit();

    // load B planes (2 x 1024 u64) from g_smh
    const uint2* gb = (const uint2*)&g_smh[(size_t)b * 2 * 16 * 64];
    #pragma unroll
    for (int k = 0; k < 16; ++k) {
        int idx = k * 128 + tid;          // 0..2047
        int pl  = idx >> 10;
        int rc  = idx & 1023;
        int rr  = rc >> 6, cc = rc & 63;
        (pl ? SB1 : SB0)[rr * 68 + cc] = gb[pl * 1024 + rr * 64 + cc];
    }

    // stage A: 64 key_cur rows -> half2 channel-pair planes (8 float4/thread)
    {
        const int rq = tid >> 4, c4 = tid & 15;
        #pragma unroll
        for (int i = 0; i < 8; ++i) {
            const int r = i * 8 + rq;
            float4 f = *(const float4*)&key_cur[(row_base + r) * C + c4 * 4];
            __half2 p0 = __floats2half2_rn(f.x, f.y);
            __half2 p1 = __floats2half2_rn(f.z, f.w);
            float r0 = f.x - __low2float(p0);
            float r1 = f.y - __high2float(p0);
            float r2 = f.z - __low2float(p1);
            float r3 = f.w - __high2float(p1);
            __half2 q0 = __floats2half2_rn(r0, r1);
            __half2 q1 = __floats2half2_rn(r2, r3);
            *(uint2*)&SA0[r * 36 + 2 * c4] = make_uint2(h2u(p0), h2u(p1));
            *(uint2*)&SA1[r * 36 + 2 * c4] = make_uint2(h2u(q0), h2u(q1));
        }
    }
    cp_wait<0>();
    __syncthreads();

    float acc[8][4];     // [n-tile][frag reg]
    #pragma unroll
    for (int nn = 0; nn < 8; ++nn)
        #pragma unroll
        for (int j = 0; j < 4; ++j) acc[nn][j] = 0.f;

    #pragma unroll
    for (int qc = 0; qc < 4; ++qc) {
        uint32_t ah0[4], ah1[4];
        const int ra = w * 16 + lq;
        const int cp = qc * 8 + lr;
        ah0[0] = SA0[ra * 36 + cp];
        ah0[1] = SA0[(ra + 8) * 36 + cp];
        ah0[2] = SA0[ra * 36 + cp + 4];
        ah0[3] = SA0[(ra + 8) * 36 + cp + 4];
        ah1[0] = SA1[ra * 36 + cp];
        ah1[1] = SA1[(ra + 8) * 36 + cp];
        ah1[2] = SA1[ra * 36 + cp + 4];
        ah1[3] = SA1[(ra + 8) * 36 + cp + 4];
        #pragma unroll
        for (int nn = 0; nn < 8; ++nn) {
            uint2 B0 = SB0[(4 * qc + lr) * 68 + nn * 8 + lq];
            uint2 B1 = SB1[(4 * qc + lr) * 68 + nn * 8 + lq];
            uint32_t b0[2] = {B0.x, B0.y};
            uint32_t b1[2] = {B1.x, B1.y};
            mma16(acc[nn], ah0, b0);
            mma16(acc[nn], ah0, b1);
            mma16(acc[nn], ah1, b0);
        }
    }

    // epilogue: add val_cur (from smem), store
    const int r0l = w * 16 + lq;
    const int r1l = r0l + 8;
    const size_t r0g = row_base + r0l;
    const size_t r1g = r0g + 8;
    #pragma unroll
    for (int nn = 0; nn < 8; ++nn) {
        const int col = nn * 8 + 2 * lr;
        float2 v0 = *(const float2*)&SV[r0l * 68 + col];
        float2 v1 = *(const float2*)&SV[r1l * 68 + col];
        stcg2(&out[r0g * C + col], acc[nn][0] + v0.x, acc[nn][1] + v0.y);
        stcg2(&out[r1g * C + col], acc[nn][2] + v1.x, acc[nn][3] + v1.y);
    }
}

// ---------------------------------------------------------------------------
extern "C" void kernel_launch(void* const* d_in, const int* in_sizes, int n_in,
                              void* d_out, int out_size)
{
    const float* key_mem = (const float*)d_in[0];
    const float* val_mem = (const float*)d_in[1];
    const float* key_cur = (const float*)d_in[2];
    const float* val_cur = (const float*)d_in[3];
    const float* alpha   = (const float*)d_in[4];
    float* out = (float*)d_out;

    cudaFuncSetAttribute(kv_partial_kernel,
                         cudaFuncAttributeMaxDynamicSharedMemorySize, KV_SMEM_BYTES);
    cudaFuncSetAttribute(out_kernel,
                         cudaFuncAttributeMaxDynamicSharedMemorySize, OUT_SMEM_BYTES);

    kv_partial_kernel<<<dim3(SPLITS, NB), 256, KV_SMEM_BYTES>>>(key_mem, val_mem);
    kv_reduce_kernel<<<128, 128>>>();
    softmax_kernel<<<1, 256>>>(alpha);
    out_kernel<<<dim3(NROWS / OROWS, NB), 128, OUT_SMEM_BYTES>>>(key_cur, val_cur, out);
}

// round 16
// speedup vs baseline: 1.0762x; 1.0472x over previous
#include <cuda_runtime.h>
#include <cuda_fp16.h>
#include <cstdint>

// ---------------------------------------------------------------------------
// Problem constants
#define NB       4
#define TOK      131072          // T*n tokens per batch
#define C        64
#define NROWS    16384           // n
#define SPLITS   128             // split-K blocks per batch
#define TPS      (TOK / SPLITS)  // 1024 tokens per block
#define STAGE_T  64              // tokens per stage
#define NSTAGES  (TPS / STAGE_T) // 16
#define RPH      72              // plane row stride in u32 (8*lr+lq -> all banks)
#define PLANEU   (32 * RPH)      // u32 per plane (32 token-pairs x 72)
#define BUFU     (4 * PLANEU)    // u32 per buffer (KH0,KH1,VH0,VH1)
#define KV_SMEM_BYTES  (2 * BUFU * 4)              // 73,728 B

#define OROWS    64              // rows per out block
#define SB64     (16 * 68)       // u64 per out B plane in smem
#define SA32     (OROWS * 36)    // u32 per out A plane in smem (row stride 36)
#define OUT_SMEM_BYTES (2 * SB64 * 8 + 2 * SA32 * 4)  // 35,840 B

// Scratch (no allocations allowed)
__device__ float g_partial[(size_t)NB * SPLITS * C * C];    // 8 MB [b][s][c][d]
__device__ float g_kv[NB * C * C];                          // [b][c][d]
// softmax output pre-split to fp16 (h0,h1) B-planes, alpha folded:
// [b][plane][row=c-quad 16][d 64] u64 = 4 halves {c,c+1 | c+8,c+9}
__device__ unsigned long long g_smh[NB * 2 * 16 * 64];

// ---- helpers ----
__device__ __forceinline__ void stcg2(float* p, float x, float y) {
    asm volatile("st.global.cg.v2.f32 [%0], {%1,%2};" :: "l"(p), "f"(x), "f"(y));
}
__device__ __forceinline__ uint32_t h2u(__half2 h) { return *(uint32_t*)&h; }

// fp16 Dekker split: x = h0 + h1 (+ O(2^-24)); pack token-pair (low = even tok)
__device__ __forceinline__ void split_pair(float a, float b,
                                           uint32_t& h0, uint32_t& h1) {
    __half ha = __float2half_rn(a);
    __half hb = __float2half_rn(b);
    float ra = a - __half2float(ha);
    float rb = b - __half2float(hb);
    __half2 p0 = __halves2half2(ha, hb);
    __half2 p1 = __floats2half2_rn(ra, rb);
    h0 = *(uint32_t*)&p0;
    h1 = *(uint32_t*)&p1;
}

// m16n8k16 fp16 HMMA: D(f32) += A(f16) x B(f16)
__device__ __forceinline__ void mma16(float* d, const uint32_t* a, const uint32_t* b) {
    asm volatile(
        "mma.sync.aligned.m16n8k16.row.col.f32.f16.f16.f32 "
        "{%0,%1,%2,%3}, {%4,%5,%6,%7}, {%8,%9}, {%0,%1,%2,%3};"
        : "+f"(d[0]), "+f"(d[1]), "+f"(d[2]), "+f"(d[3])
        : "r"(a[0]), "r"(a[1]), "r"(a[2]), "r"(a[3]), "r"(b[0]), "r"(b[1]));
}

// ---------------------------------------------------------------------------
// Kernel A: partial kv_mul on fp16 HMMA (m16n8k16, 3-product Dekker split).
// R15 layout/sync unchanged. R16 change: ANTI-CONVOY ORDERING — the stash
// (fp32->fp16 conversion) and next-stage LDG are interleaved BETWEEN the four
// MMA chunks, so the tensor pipe is busy from the first post-barrier
// instruction and the ~200 ALU insts issue in its shadow:
//   chunk0 -> stash(g0) -> chunk1 -> stash(g1) -> chunk2 -> LDG -> chunk3 -> bar
// Deps: stash@it consumes pf loaded @it-1 (stage it+1), writes buf (it+1)&1
// (not read by chunks of it); LDG(it+2) overwrites pf only after both stashes.
// ---------------------------------------------------------------------------
__global__ __launch_bounds__(256, 2) void kv_partial_kernel(
    const float* __restrict__ Kg, const float* __restrict__ Vg)
{
    extern __shared__ __align__(16) uint32_t su[];

    const int b   = blockIdx.y;
    const int sp  = blockIdx.x;
    const int tid = threadIdx.x;
    const int w   = tid >> 5;
    const int l   = tid & 31;
    const int lr  = l & 3;          // tid-in-group (k dimension)
    const int lq  = l >> 2;         // group id     (m / n dimension)
    const int c0  = (w & 3) * 16;   // warp c origin
    const int d0  = (w >> 2) * 32;  // warp d origin

    // staging: thread handles token-pairs tp and tp+16 at 16B chunk c4
    const int tp  = tid >> 4;       // 0..15
    const int c4  = tid & 15;
    const int goffA = (2 * tp) * C + c4 * 4;        // token 2tp ; +C -> 2tp+1
    const int goffB = goffA + 32 * C;               // token 2tp+32
    const int dstuA = tp * RPH + c4 * 4;
    const int dstuB = (tp + 16) * RPH + c4 * 4;

    const float* Kbase = Kg + ((size_t)b * TOK + (size_t)sp * TPS) * C;
    const float* Vbase = Vg + ((size_t)b * TOK + (size_t)sp * TPS) * C;

    float4 pf[8];   // K(2tp),K(2tp+1),V(2tp),V(2tp+1), K(2tp+32),K(2tp+33),V,V

    #define KV_LDG(adv) do {                                          \
        pf[0] = *(const float4*)(Kbase + goffA + (adv));              \
        pf[1] = *(const float4*)(Kbase + goffA + (adv) + C);          \
        pf[2] = *(const float4*)(Vbase + goffA + (adv));              \
        pf[3] = *(const float4*)(Vbase + goffA + (adv) + C);          \
        pf[4] = *(const float4*)(Kbase + goffB + (adv));              \
        pf[5] = *(const float4*)(Kbase + goffB + (adv) + C);          \
        pf[6] = *(const float4*)(Vbase + goffB + (adv));              \
        pf[7] = *(const float4*)(Vbase + goffB + (adv) + C);          \
    } while (0)

    // convert+store HALF a stage (one token-pair group) into buffer `bu`
    auto stash_one = [&](uint32_t* bu, int gsel) {
        uint32_t kh0[4], kh1[4], vh0[4], vh1[4];
        const float* ka = (const float*)&pf[gsel * 4 + 0];
        const float* kb = (const float*)&pf[gsel * 4 + 1];
        const float* va = (const float*)&pf[gsel * 4 + 2];
        const float* vb = (const float*)&pf[gsel * 4 + 3];
        #pragma unroll
        for (int j = 0; j < 4; ++j) {
            split_pair(ka[j], kb[j], kh0[j], kh1[j]);
            split_pair(va[j], vb[j], vh0[j], vh1[j]);
        }
        const int dstu = gsel ? dstuB : dstuA;
        *(uint4*)&bu[dstu]              = *(uint4*)kh0;
        *(uint4*)&bu[PLANEU + dstu]     = *(uint4*)kh1;
        *(uint4*)&bu[2 * PLANEU + dstu] = *(uint4*)vh0;
        *(uint4*)&bu[3 * PLANEU + dstu] = *(uint4*)vh1;
    };

    float acc[4][4];                 // [n-chunk][frag reg]
    #pragma unroll
    for (int i = 0; i < 4; ++i)
        #pragma unroll
        for (int j = 0; j < 4; ++j) acc[i][j] = 0.f;

    // one MMA chunk (16 tokens) of the current buffer
    auto do_chunk = [&](const uint32_t* kh0p, const uint32_t* kh1p,
                        const uint32_t* vh0p, const uint32_t* vh1p, int ch) {
        const int ra = (ch * 8 + lr) * RPH;       // k = 2lr, 2lr+1
        const int rb = (ch * 8 + lr + 4) * RPH;   // k = 2lr+8, 2lr+9
        uint32_t ah0[4], ah1[4];
        ah0[0] = kh0p[ra + c0 + lq];
        ah0[1] = kh0p[ra + c0 + lq + 8];
        ah0[2] = kh0p[rb + c0 + lq];
        ah0[3] = kh0p[rb + c0 + lq + 8];
        ah1[0] = kh1p[ra + c0 + lq];
        ah1[1] = kh1p[ra + c0 + lq + 8];
        ah1[2] = kh1p[rb + c0 + lq];
        ah1[3] = kh1p[rb + c0 + lq + 8];
        #pragma unroll
        for (int nn = 0; nn < 4; ++nn) {
            const int col = d0 + nn * 8 + lq;
            uint32_t bh0[2], bh1[2];
            bh0[0] = vh0p[ra + col];
            bh0[1] = vh0p[rb + col];
            bh1[0] = vh1p[ra + col];
            bh1[1] = vh1p[rb + col];
            mma16(acc[nn], ah0, bh0);
            mma16(acc[nn], ah0, bh1);
            mma16(acc[nn], ah1, bh0);
        }
    };

    // prologue: stage 0 -> regs -> buf0 ; stage 1 -> regs
    KV_LDG(0);
    stash_one(su, 0);
    stash_one(su, 1);
    KV_LDG(STAGE_T * C);
    __syncthreads();

    #pragma unroll 1
    for (int it = 0; it < NSTAGES; ++it) {
        const uint32_t* kh0p = &su[(it & 1) * BUFU];
        const uint32_t* kh1p = kh0p + PLANEU;
        const uint32_t* vh0p = kh0p + 2 * PLANEU;
        const uint32_t* vh1p = kh0p + 3 * PLANEU;
        uint32_t* nbuf = &su[((it + 1) & 1) * BUFU];

        do_chunk(kh0p, kh1p, vh0p, vh1p, 0);
        if (it + 1 < NSTAGES) stash_one(nbuf, 0);
        do_chunk(kh0p, kh1p, vh0p, vh1p, 1);
        if (it + 1 < NSTAGES) stash_one(nbuf, 1);
        do_chunk(kh0p, kh1p, vh0p, vh1p, 2);
        if (it + 2 < NSTAGES) KV_LDG((it + 2) * STAGE_T * C);
        do_chunk(kh0p, kh1p, vh0p, vh1p, 3);
        __syncthreads();   // compute of it done everywhere; STS of it+1 drained
    }
    #undef KV_LDG

    // epilogue: C fragment -> g_partial[b][sp][c][d]  (disjoint per warp)
    float* outp = &g_partial[((size_t)(b * SPLITS + sp)) * (C * C)];
    const int row0 = c0 + lq;
    const int row1 = row0 + 8;
    #pragma unroll
    for (int nn = 0; nn < 4; ++nn) {
        const int col = d0 + nn * 8 + 2 * lr;
        stcg2(&outp[row0 * C + col], acc[nn][0], acc[nn][1]);
        stcg2(&outp[row1 * C + col], acc[nn][2], acc[nn][3]);
    }
}

// ---------------------------------------------------------------------------
// Kernel B: deterministic split reduction v2 (R15-proven, 1.5 us).
// 128 blocks x 128 thr; 32 blocks per batch, block covers 32 consecutive
// float4. Warp j sums splits [32j, 32j+32) coalesced, fixed-order combine.
// ---------------------------------------------------------------------------
__global__ __launch_bounds__(128, 8) void kv_reduce_kernel()
{
    __shared__ float4 sums[4][32];

    const int bb   = blockIdx.x;          // 0..127
    const int b    = bb >> 5;             // batch 0..3
    const int e4   = (bb & 31) * 32;      // float4 base within batch (0..992)
    const int w    = threadIdx.x >> 5;
    const int lane = threadIdx.x & 31;

    const float4* p = (const float4*)&g_partial[(size_t)b * SPLITS * (C * C)]
                    + e4 + lane;
    float4 s0 = make_float4(0.f, 0.f, 0.f, 0.f), s1 = s0, s2 = s0, s3 = s0;
    const int base = w * 32;
    #pragma unroll 2
    for (int i = 0; i < 32; i += 4) {
        float4 t0 = p[(size_t)(base + i    ) * 1024];
        float4 t1 = p[(size_t)(base + i + 1) * 1024];
        float4 t2 = p[(size_t)(base + i + 2) * 1024];
        float4 t3 = p[(size_t)(base + i + 3) * 1024];
        s0.x += t0.x; s0.y += t0.y; s0.z += t0.z; s0.w += t0.w;
        s1.x += t1.x; s1.y += t1.y; s1.z += t1.z; s1.w += t1.w;
        s2.x += t2.x; s2.y += t2.y; s2.z += t2.z; s2.w += t2.w;
        s3.x += t3.x; s3.y += t3.y; s3.z += t3.z; s3.w += t3.w;
    }
    float4 ws;
    ws.x = (s0.x + s1.x) + (s2.x + s3.x);
    ws.y = (s0.y + s1.y) + (s2.y + s3.y);
    ws.z = (s0.z + s1.z) + (s2.z + s3.z);
    ws.w = (s0.w + s1.w) + (s2.w + s3.w);
    sums[w][lane] = ws;
    __syncthreads();

    if (w == 0) {
        float4 a = sums[0][lane], b2 = sums[1][lane];
        float4 c = sums[2][lane], d = sums[3][lane];
        float4 r;
        r.x = (a.x + b2.x) + (c.x + d.x);
        r.y = (a.y + b2.y) + (c.y + d.y);
        r.z = (a.z + b2.z) + (c.z + d.z);
        r.w = (a.w + b2.w) + (c.w + d.w);
        ((float4*)g_kv)[(size_t)b * 1024 + e4 + lane] = r;
    }
}

// ---------------------------------------------------------------------------
// Kernel C: softmax over the C axis, alpha folded; emits fp16 (h0,h1) split
// B-planes g_smh[b][plane][c-quad row][d] for the out GEMM.
// ---------------------------------------------------------------------------
__global__ void softmax_kernel(const float* __restrict__ alpha)
{
    int tid = threadIdx.x;
    int b = tid >> 6;
    int d = tid & 63;
    const float* in = &g_kv[b * (C * C) + d];

    float v[C];
    float m = -3.402823466e38f;
    #pragma unroll
    for (int c = 0; c < C; ++c) { v[c] = in[c * C]; m = fmaxf(m, v[c]); }
    float sum = 0.f;
    #pragma unroll
    for (int c = 0; c < C; ++c) { v[c] = expf(v[c] - m); sum += v[c]; }
    float sc = alpha[0] / sum;
    #pragma unroll
    for (int c = 0; c < C; ++c) v[c] *= sc;

    uint2* g0 = (uint2*)&g_smh[((size_t)b * 2 + 0) * 16 * 64];
    uint2* g1 = (uint2*)&g_smh[((size_t)b * 2 + 1) * 16 * 64];
    #pragma unroll
    for (int row = 0; row < 16; ++row) {
        const int cb = 16 * (row >> 2) + 2 * (row & 3);
        __half2 h0a = __floats2half2_rn(v[cb],     v[cb + 1]);
        __half2 h0b = __floats2half2_rn(v[cb + 8], v[cb + 9]);
        float r0 = v[cb]     - __low2float(h0a);
        float r1 = v[cb + 1] - __high2float(h0a);
        float r8 = v[cb + 8] - __low2float(h0b);
        float r9 = v[cb + 9] - __high2float(h0b);
        __half2 h1a = __floats2half2_rn(r0, r1);
        __half2 h1b = __floats2half2_rn(r8, r9);
        g0[row * 64 + d] = make_uint2(h2u(h0a), h2u(h0b));
        g1[row * 64 + d] = make_uint2(h2u(h1a), h2u(h1b));
    }
}

// ---------------------------------------------------------------------------
// Kernel D: out[b,r,d] = sum_c key_cur[b,r,c] * sm[b,c,d] + val_cur, on HMMA.
// R13-proven version (14.9 us): 64 rows/block, direct val_cur LDG epilogue
// (the R15 cp.async val prefetch regressed; reverted).
// ---------------------------------------------------------------------------
__global__ __launch_bounds__(128, 4) void out_kernel(
    const float* __restrict__ key_cur, const float* __restrict__ val_cur,
    float* __restrict__ out)
{
    extern __shared__ __align__(16) uint2 so[];
    uint2*    SB0 = so;                           // [16][68] u64
    uint2*    SB1 = so + SB64;
    uint32_t* SA0 = (uint32_t*)(so + 2 * SB64);   // [64][36] u32
    uint32_t* SA1 = SA0 + SA32;

    const int b   = blockIdx.y;
    const int rb  = blockIdx.x;       // 0..255 (64 rows each)
    const int tid = threadIdx.x;
    const int w   = tid >> 5;
    const int l   = tid & 31;
    const int lr  = l & 3;
    const int lq  = l >> 2;
    const size_t row_base = (size_t)b * NROWS + (size_t)rb * OROWS;

    // load B planes (2 x 1024 u64) from g_smh
    const uint2* gb = (const uint2*)&g_smh[(size_t)b * 2 * 16 * 64];
    #pragma unroll
    for (int k = 0; k < 16; ++k) {
        int idx = k * 128 + tid;          // 0..2047
        int pl  = idx >> 10;
        int rc  = idx & 1023;
        int rr  = rc >> 6, cc = rc & 63;
        (pl ? SB1 : SB0)[rr * 68 + cc] = gb[pl * 1024 + rr * 64 + cc];
    }

    // stage A: 64 key_cur rows -> half2 channel-pair planes (8 float4/thread)
    {
        const int rq = tid >> 4, c4 = tid & 15;
        #pragma unroll
        for (int i = 0; i < 8; ++i) {
            const int r = i * 8 + rq;
            float4 f = *(const float4*)&key_cur[(row_base + r) * C + c4 * 4];
            __half2 p0 = __floats2half2_rn(f.x, f.y);
            __half2 p1 = __floats2half2_rn(f.z, f.w);
            float r0 = f.x - __low2float(p0);
            float r1 = f.y - __high2float(p0);
            float r2 = f.z - __low2float(p1);
            float r3 = f.w - __high2float(p1);
            __half2 q0 = __floats2half2_rn(r0, r1);
            __half2 q1 = __floats2half2_rn(r2, r3);
            *(uint2*)&SA0[r * 36 + 2 * c4] = make_uint2(h2u(p0), h2u(p1));
            *(uint2*)&SA1[r * 36 + 2 * c4] = make_uint2(h2u(q0), h2u(q1));
        }
    }
    __syncthreads();

    float acc[8][4];     // [n-tile][frag reg]
    #pragma unroll
    for (int nn = 0; nn < 8; ++nn)
        #pragma unroll
        for (int j = 0; j < 4; ++j) acc[nn][j] = 0.f;

    #pragma unroll
    for (int qc = 0; qc < 4; ++qc) {
        uint32_t ah0[4], ah1[4];
        const int ra = w * 16 + lq;
        const int cp = qc * 8 + lr;
        ah0[0] = SA0[ra * 36 + cp];
        ah0[1] = SA0[(ra + 8) * 36 + cp];
        ah0[2] = SA0[ra * 36 + cp + 4];
        ah0[3] = SA0[(ra + 8) * 36 + cp + 4];
        ah1[0] = SA1[ra * 36 + cp];
        ah1[1] = SA1[(ra + 8) * 36 + cp];
        ah1[2] = SA1[ra * 36 + cp + 4];
        ah1[3] = SA1[(ra + 8) * 36 + cp + 4];
        #pragma unroll
        for (int nn = 0; nn < 8; ++nn) {
            uint2 B0 = SB0[(4 * qc + lr) * 68 + nn * 8 + lq];
            uint2 B1 = SB1[(4 * qc + lr) * 68 + nn * 8 + lq];
            uint32_t b0[2] = {B0.x, B0.y};
            uint32_t b1[2] = {B1.x, B1.y};
            mma16(acc[nn], ah0, b0);
            mma16(acc[nn], ah0, b1);
            mma16(acc[nn], ah1, b0);
        }
    }

    // epilogue: add val_cur, store
    const size_t r0g = row_base + w * 16 + lq;
    const size_t r1g = r0g + 8;
    #pragma unroll
    for (int nn = 0; nn < 8; ++nn) {
        const int col = nn * 8 + 2 * lr;
        float2 v0 = *(const float2*)&val_cur[r0g * C + col];
        float2 v1 = *(const float2*)&val_cur[r1g * C + col];
        stcg2(&out[r0g * C + col], acc[nn][0] + v0.x, acc[nn][1] + v0.y);
        stcg2(&out[r1g * C + col], acc[nn][2] + v1.x, acc[nn][3] + v1.y);
    }
}

// ---------------------------------------------------------------------------
extern "C" void kernel_launch(void* const* d_in, const int* in_sizes, int n_in,
                              void* d_out, int out_size)
{
    const float* key_mem = (const float*)d_in[0];
    const float* val_mem = (const float*)d_in[1];
    const float* key_cur = (const float*)d_in[2];
    const float* val_cur = (const float*)d_in[3];
    const float* alpha   = (const float*)d_in[4];
    float* out = (float*)d_out;

    cudaFuncSetAttribute(kv_partial_kernel,
                         cudaFuncAttributeMaxDynamicSharedMemorySize, KV_SMEM_BYTES);
    cudaFuncSetAttribute(out_kernel,
                         cudaFuncAttributeMaxDynamicSharedMemorySize, OUT_SMEM_BYTES);

    kv_partial_kernel<<<dim3(SPLITS, NB), 256, KV_SMEM_BYTES>>>(key_mem, val_mem);
    kv_reduce_kernel<<<128, 128>>>();
    softmax_kernel<<<1, 256>>>(alpha);
    out_kernel<<<dim3(NROWS / OROWS, NB), 128, OUT_SMEM_BYTES>>>(key_cur, val_cur, out);
}